// round 11
// baseline (speedup 1.0000x reference)
#include <cuda_runtime.h>
#include <cuda_fp16.h>

#define N_NODES 100000
#define E_EDGES 1600000
#define D 64
#define SCAN_BS 1024
#define SCAN_NB ((N_NODES + SCAN_BS - 1) / SCAN_BS)   // 98

// ---------------- scratch (static device globals; no allocation) ------------
__device__ uint2 g_hsh[N_NODES * 16];    // (h @ W) * dinv[row], fp16 (4 halves/uint2)
__device__ float g_h  [N_NODES * D];     // layer output ping buffer (fp32)
__device__ float g_dinv[N_NODES];
__device__ int   g_cnt[N_NODES];         // in-degree counts
__device__ int   g_row_start[N_NODES + 1];
__device__ int   g_cursor[N_NODES];
__device__ int   g_edge_src[E_EDGES];    // src ids grouped by dst (CSR)
__device__ int   g_bsum[SCAN_NB];
__device__ int   g_is64;                 // 1 if edge_index buffer is int64

// ---------------- zero counts + dtype detection (merged) --------------------
__global__ void zero_detect_k(const int* __restrict__ ei32) {
    int i = blockIdx.x * blockDim.x + threadIdx.x;
    if (i < N_NODES) g_cnt[i] = 0;
    if (i == 0) {
        int nz = 0;
        #pragma unroll
        for (int k = 0; k < 8; k++) nz |= ei32[2 * k + 1];
        g_is64 = (nz == 0) ? 1 : 0;
    }
}

// decode dst + degree histogram, 4 edges per thread (int4 path for int32)
__global__ void hist_k(const void* __restrict__ eiv) {
    int e0 = (blockIdx.x * blockDim.x + threadIdx.x) * 4;
    if (e0 >= E_EDGES) return;
    if (g_is64) {
        const long long* ei = (const long long*)eiv;
        #pragma unroll
        for (int q = 0; q < 4; q++) {
            int d = (int)ei[E_EDGES + e0 + q];
            d = min(max(d, 0), N_NODES - 1);
            atomicAdd(&g_cnt[d], 1);
        }
    } else {
        int4 dv = *(const int4*)((const int*)eiv + E_EDGES + e0);
        atomicAdd(&g_cnt[min(max(dv.x, 0), N_NODES - 1)], 1);
        atomicAdd(&g_cnt[min(max(dv.y, 0), N_NODES - 1)], 1);
        atomicAdd(&g_cnt[min(max(dv.z, 0), N_NODES - 1)], 1);
        atomicAdd(&g_cnt[min(max(dv.w, 0), N_NODES - 1)], 1);
    }
}

// shuffle-based block scan (2 barriers)
__global__ void scan1_k() {
    __shared__ int warp_sums[32];
    int tid  = threadIdx.x;
    int wid  = tid >> 5;
    int lane = tid & 31;
    int i = blockIdx.x * SCAN_BS + tid;
    int v = (i < N_NODES) ? g_cnt[i] : 0;

    int incl = v;
    #pragma unroll
    for (int off = 1; off < 32; off <<= 1) {
        int t = __shfl_up_sync(0xffffffffu, incl, off);
        if (lane >= off) incl += t;
    }
    if (lane == 31) warp_sums[wid] = incl;
    __syncthreads();
    if (wid == 0) {
        int ws = warp_sums[lane];
        int wincl = ws;
        #pragma unroll
        for (int off = 1; off < 32; off <<= 1) {
            int t = __shfl_up_sync(0xffffffffu, wincl, off);
            if (lane >= off) wincl += t;
        }
        warp_sums[lane] = wincl - ws;
        if (lane == 31) g_bsum[blockIdx.x] = wincl;
    }
    __syncthreads();
    if (i < N_NODES) g_row_start[i] = warp_sums[wid] + incl - v;
}

// scan3 with scan2 folded in
__global__ void scan3_k() {
    __shared__ int sboff[2];
    int i0  = blockIdx.x * 256;
    int sb0 = i0 >> 10;
    int sb1 = (i0 + 255) >> 10;
    int wid = threadIdx.x >> 5, lane = threadIdx.x & 31;
    if (wid < 2) {
        int target = (wid == 0) ? sb0 : sb1;
        int s = 0;
        for (int b = lane; b < target; b += 32) s += g_bsum[b];
        #pragma unroll
        for (int off = 16; off; off >>= 1) s += __shfl_down_sync(0xffffffffu, s, off);
        if (lane == 0) sboff[wid] = s;
    }
    __syncthreads();
    int i = i0 + threadIdx.x;
    if (i < N_NODES) {
        int off = sboff[((i >> 10) == sb0) ? 0 : 1];
        int rs = g_row_start[i] + off;
        g_row_start[i] = rs;
        g_cursor[i]    = rs;
        g_dinv[i]      = rsqrtf((float)g_cnt[i] + 1.0f);
    }
    if (i == 0) g_row_start[N_NODES] = E_EDGES;
}

// scatter src into CSR slots, 4 edges per thread (int4 path for int32)
__global__ void place_k(const void* __restrict__ eiv) {
    int e0 = (blockIdx.x * blockDim.x + threadIdx.x) * 4;
    if (e0 >= E_EDGES) return;
    if (g_is64) {
        const long long* ei = (const long long*)eiv;
        #pragma unroll
        for (int q = 0; q < 4; q++) {
            int s = (int)ei[e0 + q];
            int d = (int)ei[E_EDGES + e0 + q];
            s = min(max(s, 0), N_NODES - 1);
            d = min(max(d, 0), N_NODES - 1);
            int pos = atomicAdd(&g_cursor[d], 1);
            g_edge_src[pos] = s;
        }
    } else {
        const int* ei = (const int*)eiv;
        int4 sv = *(const int4*)(ei + e0);
        int4 dv = *(const int4*)(ei + E_EDGES + e0);
        int ss[4] = {sv.x, sv.y, sv.z, sv.w};
        int dd[4] = {dv.x, dv.y, dv.z, dv.w};
        #pragma unroll
        for (int q = 0; q < 4; q++) {
            int s = min(max(ss[q], 0), N_NODES - 1);
            int d = min(max(dd[q], 0), N_NODES - 1);
            int pos = atomicAdd(&g_cursor[d], 1);
            g_edge_src[pos] = s;
        }
    }
}

// ---------------- fused GEMM: hsh = fp16((in @ W) * dinv[row]) --------------
// Block tile 128 rows x 64 cols, 128 threads, 8x8 register tile per thread.
// K processed in 2 chunks of 32 so smem fits: Ws 17408 + xT 16896 = 34304 B.
#define WPAD 68
#define XPAD 132
__global__ void __launch_bounds__(128)
gemm_scale_k(const float* __restrict__ xg, const float* __restrict__ W) {
    __shared__ float Ws[64 * WPAD];
    __shared__ float xT[32 * XPAD];

    const float* in = xg ? xg : g_h;
    const int tid  = threadIdx.x;
    const int row0 = blockIdx.x * 128;

    // load W (64x64) coalesced
    for (int i4 = tid; i4 < 1024; i4 += 128) {
        float4 v = ((const float4*)W)[i4];
        int lin = i4 * 4;
        int k = lin >> 6, c = lin & 63;
        *(float4*)&Ws[k * WPAD + c] = v;
    }

    const int c0 = (tid & 7) * 8;     // 8 consecutive output cols
    const int r0 = (tid >> 3) * 8;    // 8 consecutive rows
    const int rg = row0 + tid;        // this thread's x row to stage

    float acc[8][8] = {};

    #pragma unroll
    for (int chunk = 0; chunk < 2; chunk++) {
        __syncthreads();   // protect xT overwrite (and W load on first pass)
        // stage x rows for k in [chunk*32, chunk*32+32), transposed
        if (rg < N_NODES) {
            const float4* xrow = (const float4*)(in + (size_t)rg * D) + chunk * 8;
            #pragma unroll
            for (int kq = 0; kq < 8; kq++) {
                float4 v = xrow[kq];
                int k = kq * 4;
                xT[(k + 0) * XPAD + tid] = v.x;
                xT[(k + 1) * XPAD + tid] = v.y;
                xT[(k + 2) * XPAD + tid] = v.z;
                xT[(k + 3) * XPAD + tid] = v.w;
            }
        } else {
            #pragma unroll 8
            for (int k = 0; k < 32; k++) xT[k * XPAD + tid] = 0.f;
        }
        __syncthreads();

        #pragma unroll 4
        for (int kk = 0; kk < 32; kk++) {
            int k = chunk * 32 + kk;
            float4 w0 = *(float4*)&Ws[k * WPAD + c0];
            float4 w1 = *(float4*)&Ws[k * WPAD + c0 + 4];
            float4 x0 = *(float4*)&xT[kk * XPAD + r0];
            float4 x1 = *(float4*)&xT[kk * XPAD + r0 + 4];
            float xr[8] = {x0.x, x0.y, x0.z, x0.w, x1.x, x1.y, x1.z, x1.w};
            float wc[8] = {w0.x, w0.y, w0.z, w0.w, w1.x, w1.y, w1.z, w1.w};
            #pragma unroll
            for (int i = 0; i < 8; i++)
                #pragma unroll
                for (int j = 0; j < 8; j++)
                    acc[i][j] += xr[i] * wc[j];
        }
    }

    #pragma unroll
    for (int i = 0; i < 8; i++) {
        int row = row0 + r0 + i;
        if (row < N_NODES) {
            float dv = g_dinv[row];
            __half2 h0 = __floats2half2_rn(acc[i][0] * dv, acc[i][1] * dv);
            __half2 h1 = __floats2half2_rn(acc[i][2] * dv, acc[i][3] * dv);
            __half2 h2 = __floats2half2_rn(acc[i][4] * dv, acc[i][5] * dv);
            __half2 h3 = __floats2half2_rn(acc[i][6] * dv, acc[i][7] * dv);
            uint2 u0, u1;
            u0.x = *(unsigned*)&h0; u0.y = *(unsigned*)&h1;
            u1.x = *(unsigned*)&h2; u1.y = *(unsigned*)&h3;
            g_hsh[(size_t)row * 16 + (c0 >> 2)]     = u0;
            g_hsh[(size_t)row * 16 + (c0 >> 2) + 1] = u1;
        }
    }
}

// ---------------- CSR gather + epilogue -------------------------------------
// Half-warp per node, shuffle-batched index loads (16 gathers in flight).
__global__ void __launch_bounds__(256)
agg_k(const float* __restrict__ b, float* __restrict__ outp, int relu) {
    int warp  = (blockIdx.x * blockDim.x + threadIdx.x) >> 5;
    int lane  = threadIdx.x & 31;
    int half  = lane >> 4;
    int l     = lane & 15;
    int node  = warp * 2 + half;
    if (node >= N_NODES) return;

    unsigned hmask = half ? 0xffff0000u : 0x0000ffffu;
    float* out = outp ? outp : g_h;

    int beg = g_row_start[node];
    int end = g_row_start[node + 1];

    float4 acc;
    {   // self-loop term
        uint2 u = __ldg(&g_hsh[(size_t)node * 16 + l]);
        float2 f0 = __half22float2(*(__half2*)&u.x);
        float2 f1 = __half22float2(*(__half2*)&u.y);
        acc = make_float4(f0.x, f0.y, f1.x, f1.y);
    }

    for (int base = beg; base < end; base += 16) {
        int n = end - base; if (n > 16) n = 16;
        int myidx = (l < n) ? __ldg(&g_edge_src[base + l]) : 0;
        int j = 0;
        for (; j + 3 < n; j += 4) {
            int s0 = __shfl_sync(hmask, myidx, j + 0, 16);
            int s1 = __shfl_sync(hmask, myidx, j + 1, 16);
            int s2 = __shfl_sync(hmask, myidx, j + 2, 16);
            int s3 = __shfl_sync(hmask, myidx, j + 3, 16);
            uint2 u0 = __ldg(&g_hsh[(size_t)s0 * 16 + l]);
            uint2 u1 = __ldg(&g_hsh[(size_t)s1 * 16 + l]);
            uint2 u2 = __ldg(&g_hsh[(size_t)s2 * 16 + l]);
            uint2 u3 = __ldg(&g_hsh[(size_t)s3 * 16 + l]);
            float2 a0 = __half22float2(*(__half2*)&u0.x), c0 = __half22float2(*(__half2*)&u0.y);
            float2 a1 = __half22float2(*(__half2*)&u1.x), c1 = __half22float2(*(__half2*)&u1.y);
            float2 a2 = __half22float2(*(__half2*)&u2.x), c2 = __half22float2(*(__half2*)&u2.y);
            float2 a3 = __half22float2(*(__half2*)&u3.x), c3 = __half22float2(*(__half2*)&u3.y);
            acc.x += (a0.x + a1.x) + (a2.x + a3.x);
            acc.y += (a0.y + a1.y) + (a2.y + a3.y);
            acc.z += (c0.x + c1.x) + (c2.x + c3.x);
            acc.w += (c0.y + c1.y) + (c2.y + c3.y);
        }
        for (; j < n; j++) {
            int s0 = __shfl_sync(hmask, myidx, j, 16);
            uint2 u = __ldg(&g_hsh[(size_t)s0 * 16 + l]);
            float2 f0 = __half22float2(*(__half2*)&u.x);
            float2 f1 = __half22float2(*(__half2*)&u.y);
            acc.x += f0.x; acc.y += f0.y; acc.z += f1.x; acc.w += f1.y;
        }
    }

    float dv = g_dinv[node];
    float4 bv = __ldg(&((const float4*)b)[l]);
    float4 o;
    o.x = acc.x * dv + bv.x;
    o.y = acc.y * dv + bv.y;
    o.z = acc.z * dv + bv.z;
    o.w = acc.w * dv + bv.w;
    if (relu) {
        o.x = fmaxf(o.x, 0.f); o.y = fmaxf(o.y, 0.f);
        o.z = fmaxf(o.z, 0.f); o.w = fmaxf(o.w, 0.f);
    }
    ((float4*)out)[(size_t)node * 16 + l] = o;
}

// ---------------- launch ----------------------------------------------------
extern "C" void kernel_launch(void* const* d_in, const int* in_sizes, int n_in,
                              void* d_out, int out_size) {
    const float* x  = (const float*)d_in[0];
    const void*  ei = d_in[1];                 // int32 (or int64), detected on device
    const float* W0 = (const float*)d_in[2];
    const float* b0 = (const float*)d_in[3];
    const float* W1 = (const float*)d_in[4];
    const float* b1 = (const float*)d_in[5];
    const float* W2 = (const float*)d_in[6];
    const float* b2 = (const float*)d_in[7];
    float* out = (float*)d_out;

    const int TB = 256;
    const int ngrid  = (N_NODES + TB - 1) / TB;
    const int e4grid = (E_EDGES / 4 + TB - 1) / TB;   // 4 edges per thread

    zero_detect_k<<<ngrid, TB>>>((const int*)ei);
    hist_k       <<<e4grid, TB>>>(ei);
    scan1_k      <<<SCAN_NB, SCAN_BS>>>();
    scan3_k      <<<ngrid, TB>>>();
    place_k      <<<e4grid, TB>>>(ei);

    const int gemm_grid = (N_NODES + 127) / 128;
    const int agg_grid  = ((N_NODES + 1) / 2 * 32 + TB - 1) / TB;  // 2 nodes/warp

    // layer 0
    gemm_scale_k<<<gemm_grid, 128>>>(x, W0);
    agg_k       <<<agg_grid, TB>>>(b0, nullptr, 1);
    // layer 1
    gemm_scale_k<<<gemm_grid, 128>>>(nullptr, W1);
    agg_k       <<<agg_grid, TB>>>(b1, nullptr, 1);
    // layer 2 -> d_out, no relu
    gemm_scale_k<<<gemm_grid, 128>>>(nullptr, W2);
    agg_k       <<<agg_grid, TB>>>(b2, out, 0);
}

// round 12
// speedup vs baseline: 1.0935x; 1.0935x over previous
#include <cuda_runtime.h>
#include <cuda_fp16.h>

#define N_NODES 100000
#define E_EDGES 1600000
#define D 64
#define SCAN_BS 1024
#define SCAN_NB ((N_NODES + SCAN_BS - 1) / SCAN_BS)   // 98

// ---------------- scratch (static device globals; no allocation) ------------
__device__ uint2 g_hsh[N_NODES * 16];    // (h @ W) * dinv[row], fp16 (4 halves/uint2)
__device__ float g_h  [N_NODES * D];     // layer output ping buffer (fp32)
__device__ float g_dinv[N_NODES];
__device__ int   g_cnt[N_NODES];         // in-degree counts
__device__ int   g_row_start[N_NODES + 1];
__device__ int   g_cursor[N_NODES];
__device__ int   g_edge_src[E_EDGES];    // src ids grouped by dst (CSR)
__device__ int   g_bsum[SCAN_NB];
__device__ int   g_is64;                 // 1 if edge_index buffer is int64

// ---------------- zero counts + dtype detection (merged) --------------------
__global__ void zero_detect_k(const int* __restrict__ ei32) {
    int i = blockIdx.x * blockDim.x + threadIdx.x;
    if (i < N_NODES) g_cnt[i] = 0;
    if (i == 0) {
        int nz = 0;
        #pragma unroll
        for (int k = 0; k < 8; k++) nz |= ei32[2 * k + 1];
        g_is64 = (nz == 0) ? 1 : 0;
    }
}

// decode dst + degree histogram, 4 edges per thread (int4 path for int32)
__global__ void hist_k(const void* __restrict__ eiv) {
    int e0 = (blockIdx.x * blockDim.x + threadIdx.x) * 4;
    if (e0 >= E_EDGES) return;
    if (g_is64) {
        const long long* ei = (const long long*)eiv;
        #pragma unroll
        for (int q = 0; q < 4; q++) {
            int d = (int)ei[E_EDGES + e0 + q];
            d = min(max(d, 0), N_NODES - 1);
            atomicAdd(&g_cnt[d], 1);
        }
    } else {
        int4 dv = *(const int4*)((const int*)eiv + E_EDGES + e0);
        atomicAdd(&g_cnt[min(max(dv.x, 0), N_NODES - 1)], 1);
        atomicAdd(&g_cnt[min(max(dv.y, 0), N_NODES - 1)], 1);
        atomicAdd(&g_cnt[min(max(dv.z, 0), N_NODES - 1)], 1);
        atomicAdd(&g_cnt[min(max(dv.w, 0), N_NODES - 1)], 1);
    }
}

// shuffle-based block scan (2 barriers)
__global__ void scan1_k() {
    __shared__ int warp_sums[32];
    int tid  = threadIdx.x;
    int wid  = tid >> 5;
    int lane = tid & 31;
    int i = blockIdx.x * SCAN_BS + tid;
    int v = (i < N_NODES) ? g_cnt[i] : 0;

    int incl = v;
    #pragma unroll
    for (int off = 1; off < 32; off <<= 1) {
        int t = __shfl_up_sync(0xffffffffu, incl, off);
        if (lane >= off) incl += t;
    }
    if (lane == 31) warp_sums[wid] = incl;
    __syncthreads();
    if (wid == 0) {
        int ws = warp_sums[lane];
        int wincl = ws;
        #pragma unroll
        for (int off = 1; off < 32; off <<= 1) {
            int t = __shfl_up_sync(0xffffffffu, wincl, off);
            if (lane >= off) wincl += t;
        }
        warp_sums[lane] = wincl - ws;
        if (lane == 31) g_bsum[blockIdx.x] = wincl;
    }
    __syncthreads();
    if (i < N_NODES) g_row_start[i] = warp_sums[wid] + incl - v;
}

// scan3 with scan2 folded in
__global__ void scan3_k() {
    __shared__ int sboff[2];
    int i0  = blockIdx.x * 256;
    int sb0 = i0 >> 10;
    int sb1 = (i0 + 255) >> 10;
    int wid = threadIdx.x >> 5, lane = threadIdx.x & 31;
    if (wid < 2) {
        int target = (wid == 0) ? sb0 : sb1;
        int s = 0;
        for (int b = lane; b < target; b += 32) s += g_bsum[b];
        #pragma unroll
        for (int off = 16; off; off >>= 1) s += __shfl_down_sync(0xffffffffu, s, off);
        if (lane == 0) sboff[wid] = s;
    }
    __syncthreads();
    int i = i0 + threadIdx.x;
    if (i < N_NODES) {
        int off = sboff[((i >> 10) == sb0) ? 0 : 1];
        int rs = g_row_start[i] + off;
        g_row_start[i] = rs;
        g_cursor[i]    = rs;
        g_dinv[i]      = rsqrtf((float)g_cnt[i] + 1.0f);
    }
    if (i == 0) g_row_start[N_NODES] = E_EDGES;
}

// scatter src into CSR slots, 4 edges per thread (int4 path for int32)
__global__ void place_k(const void* __restrict__ eiv) {
    int e0 = (blockIdx.x * blockDim.x + threadIdx.x) * 4;
    if (e0 >= E_EDGES) return;
    if (g_is64) {
        const long long* ei = (const long long*)eiv;
        #pragma unroll
        for (int q = 0; q < 4; q++) {
            int s = (int)ei[e0 + q];
            int d = (int)ei[E_EDGES + e0 + q];
            s = min(max(s, 0), N_NODES - 1);
            d = min(max(d, 0), N_NODES - 1);
            int pos = atomicAdd(&g_cursor[d], 1);
            g_edge_src[pos] = s;
        }
    } else {
        const int* ei = (const int*)eiv;
        int4 sv = *(const int4*)(ei + e0);
        int4 dv = *(const int4*)(ei + E_EDGES + e0);
        int ss[4] = {sv.x, sv.y, sv.z, sv.w};
        int dd[4] = {dv.x, dv.y, dv.z, dv.w};
        #pragma unroll
        for (int q = 0; q < 4; q++) {
            int s = min(max(ss[q], 0), N_NODES - 1);
            int d = min(max(dd[q], 0), N_NODES - 1);
            int pos = atomicAdd(&g_cursor[d], 1);
            g_edge_src[pos] = s;
        }
    }
}

// ---------------- fused GEMM: hsh = fp16((in @ W) * dinv[row]) --------------
// R9 configuration: 64x64 tile, 256 threads, 4x4 register tile (best measured).
#define WPAD 68
__global__ void __launch_bounds__(256)
gemm_scale_k(const float* __restrict__ xg, const float* __restrict__ W) {
    __shared__ float Ws[64 * WPAD];
    __shared__ float xT[64 * WPAD];

    const float* in = xg ? xg : g_h;
    const int tid  = threadIdx.x;
    const int row0 = blockIdx.x * 64;

    for (int i4 = tid; i4 < 1024; i4 += 256) {
        float4 v = ((const float4*)W)[i4];
        int lin = i4 * 4;
        int k = lin >> 6, c = lin & 63;
        *(float4*)&Ws[k * WPAD + c] = v;
    }
    {
        int r  = tid >> 2;
        int kq = (tid & 3) * 16;
        int rg = row0 + r;
        const float4* xrow = (const float4*)(in + (size_t)rg * D);
        #pragma unroll
        for (int kk = 0; kk < 16; kk += 4) {
            float4 v = (rg < N_NODES) ? xrow[(kq + kk) >> 2]
                                      : make_float4(0.f, 0.f, 0.f, 0.f);
            int k = kq + kk;
            xT[(k + 0) * WPAD + r] = v.x;
            xT[(k + 1) * WPAD + r] = v.y;
            xT[(k + 2) * WPAD + r] = v.z;
            xT[(k + 3) * WPAD + r] = v.w;
        }
    }
    __syncthreads();

    const int c0 = (tid & 15) * 4;
    const int r0 = (tid >> 4) * 4;

    float acc[4][4];
    #pragma unroll
    for (int i = 0; i < 4; i++)
        #pragma unroll
        for (int j = 0; j < 4; j++) acc[i][j] = 0.0f;

    #pragma unroll 16
    for (int k = 0; k < 64; k++) {
        float4 wv = *(float4*)&Ws[k * WPAD + c0];
        float4 xv = *(float4*)&xT[k * WPAD + r0];
        acc[0][0] += xv.x * wv.x; acc[0][1] += xv.x * wv.y;
        acc[0][2] += xv.x * wv.z; acc[0][3] += xv.x * wv.w;
        acc[1][0] += xv.y * wv.x; acc[1][1] += xv.y * wv.y;
        acc[1][2] += xv.y * wv.z; acc[1][3] += xv.y * wv.w;
        acc[2][0] += xv.z * wv.x; acc[2][1] += xv.z * wv.y;
        acc[2][2] += xv.z * wv.z; acc[2][3] += xv.z * wv.w;
        acc[3][0] += xv.w * wv.x; acc[3][1] += xv.w * wv.y;
        acc[3][2] += xv.w * wv.z; acc[3][3] += xv.w * wv.w;
    }

    #pragma unroll
    for (int i = 0; i < 4; i++) {
        int row = row0 + r0 + i;
        if (row < N_NODES) {
            float dv = g_dinv[row];
            __half2 h0 = __floats2half2_rn(acc[i][0] * dv, acc[i][1] * dv);
            __half2 h1 = __floats2half2_rn(acc[i][2] * dv, acc[i][3] * dv);
            uint2 u;
            u.x = *(unsigned*)&h0;
            u.y = *(unsigned*)&h1;
            g_hsh[(size_t)row * 16 + (c0 >> 2)] = u;
        }
    }
}

// ---------------- CSR gather + epilogue -------------------------------------
// Half-warp per node, shuffle-batched index loads (16 gathers in flight).
__global__ void __launch_bounds__(256)
agg_k(const float* __restrict__ b, float* __restrict__ outp, int relu) {
    int warp  = (blockIdx.x * blockDim.x + threadIdx.x) >> 5;
    int lane  = threadIdx.x & 31;
    int half  = lane >> 4;
    int l     = lane & 15;
    int node  = warp * 2 + half;
    if (node >= N_NODES) return;

    unsigned hmask = half ? 0xffff0000u : 0x0000ffffu;
    float* out = outp ? outp : g_h;

    int beg = g_row_start[node];
    int end = g_row_start[node + 1];

    float4 acc;
    {   // self-loop term
        uint2 u = __ldg(&g_hsh[(size_t)node * 16 + l]);
        float2 f0 = __half22float2(*(__half2*)&u.x);
        float2 f1 = __half22float2(*(__half2*)&u.y);
        acc = make_float4(f0.x, f0.y, f1.x, f1.y);
    }

    for (int base = beg; base < end; base += 16) {
        int n = end - base; if (n > 16) n = 16;
        int myidx = (l < n) ? __ldg(&g_edge_src[base + l]) : 0;
        int j = 0;
        for (; j + 3 < n; j += 4) {
            int s0 = __shfl_sync(hmask, myidx, j + 0, 16);
            int s1 = __shfl_sync(hmask, myidx, j + 1, 16);
            int s2 = __shfl_sync(hmask, myidx, j + 2, 16);
            int s3 = __shfl_sync(hmask, myidx, j + 3, 16);
            uint2 u0 = __ldg(&g_hsh[(size_t)s0 * 16 + l]);
            uint2 u1 = __ldg(&g_hsh[(size_t)s1 * 16 + l]);
            uint2 u2 = __ldg(&g_hsh[(size_t)s2 * 16 + l]);
            uint2 u3 = __ldg(&g_hsh[(size_t)s3 * 16 + l]);
            float2 a0 = __half22float2(*(__half2*)&u0.x), c0 = __half22float2(*(__half2*)&u0.y);
            float2 a1 = __half22float2(*(__half2*)&u1.x), c1 = __half22float2(*(__half2*)&u1.y);
            float2 a2 = __half22float2(*(__half2*)&u2.x), c2 = __half22float2(*(__half2*)&u2.y);
            float2 a3 = __half22float2(*(__half2*)&u3.x), c3 = __half22float2(*(__half2*)&u3.y);
            acc.x += (a0.x + a1.x) + (a2.x + a3.x);
            acc.y += (a0.y + a1.y) + (a2.y + a3.y);
            acc.z += (c0.x + c1.x) + (c2.x + c3.x);
            acc.w += (c0.y + c1.y) + (c2.y + c3.y);
        }
        for (; j < n; j++) {
            int s0 = __shfl_sync(hmask, myidx, j, 16);
            uint2 u = __ldg(&g_hsh[(size_t)s0 * 16 + l]);
            float2 f0 = __half22float2(*(__half2*)&u.x);
            float2 f1 = __half22float2(*(__half2*)&u.y);
            acc.x += f0.x; acc.y += f0.y; acc.z += f1.x; acc.w += f1.y;
        }
    }

    float dv = g_dinv[node];
    float4 bv = __ldg(&((const float4*)b)[l]);
    float4 o;
    o.x = acc.x * dv + bv.x;
    o.y = acc.y * dv + bv.y;
    o.z = acc.z * dv + bv.z;
    o.w = acc.w * dv + bv.w;
    if (relu) {
        o.x = fmaxf(o.x, 0.f); o.y = fmaxf(o.y, 0.f);
        o.z = fmaxf(o.z, 0.f); o.w = fmaxf(o.w, 0.f);
    }
    ((float4*)out)[(size_t)node * 16 + l] = o;
}

// ---------------- launch ----------------------------------------------------
extern "C" void kernel_launch(void* const* d_in, const int* in_sizes, int n_in,
                              void* d_out, int out_size) {
    const float* x  = (const float*)d_in[0];
    const void*  ei = d_in[1];                 // int32 (or int64), detected on device
    const float* W0 = (const float*)d_in[2];
    const float* b0 = (const float*)d_in[3];
    const float* W1 = (const float*)d_in[4];
    const float* b1 = (const float*)d_in[5];
    const float* W2 = (const float*)d_in[6];
    const float* b2 = (const float*)d_in[7];
    float* out = (float*)d_out;

    const int TB = 256;
    const int ngrid  = (N_NODES + TB - 1) / TB;
    const int e4grid = (E_EDGES / 4 + TB - 1) / TB;   // 4 edges per thread

    zero_detect_k<<<ngrid, TB>>>((const int*)ei);
    hist_k       <<<e4grid, TB>>>(ei);
    scan1_k      <<<SCAN_NB, SCAN_BS>>>();
    scan3_k      <<<ngrid, TB>>>();
    place_k      <<<e4grid, TB>>>(ei);

    const int gemm_grid = (N_NODES + 63) / 64;
    const int agg_grid  = ((N_NODES + 1) / 2 * 32 + TB - 1) / TB;  // 2 nodes/warp

    // layer 0
    gemm_scale_k<<<gemm_grid, TB>>>(x, W0);
    agg_k       <<<agg_grid, TB>>>(b0, nullptr, 1);
    // layer 1
    gemm_scale_k<<<gemm_grid, TB>>>(nullptr, W1);
    agg_k       <<<agg_grid, TB>>>(b1, nullptr, 1);
    // layer 2 -> d_out, no relu
    gemm_scale_k<<<gemm_grid, TB>>>(nullptr, W2);
    agg_k       <<<agg_grid, TB>>>(b2, out, 0);
}